// round 16
// baseline (speedup 1.0000x reference)
#include <cuda_runtime.h>
#include <cuda_bf16.h>
#include <cstdint>

#define NPIX 262144               // 512*512 = 2^18
#define HALFCNT 4194304u          // 2^22 threefry counter half
#define GBLK 1024                 // k_gramB blocks (256 px each)

// ---------------- device scratch (allocation-free) ----------------
__device__ float g_xt[4 * 210];
__device__ float g_acoef[4 * 8 * 2 * 6];  // [b][r][j][bb0,bb1,p,q,u,v]
__device__ float g_wr[4 * 8];
__device__ float g_part[4 * 44 * GBLK];   // gram partials [b*44+j][blk]
__device__ float g_w[32 * NPIX];          // w[b*8+r][n] plane-major (32 MiB)
__device__ float g_Cc[4 * 8];
__device__ float g_Ff[4 * 8];
__device__ float g_Kk[4];
__device__ int   g_ctr;                   // last-block counter (reset each run)

__global__ void k_nop() {}

// ---------------- K0: fused xt + mods (last block does mods) ----------------
__global__ void k_pre(const float* __restrict__ x, const float* __restrict__ cw,
                      const float* __restrict__ cb) {
  int f = blockIdx.x;          // 0..209
  int t = threadIdx.x;         // 128
  {
    const float* wrow = cw + f * 512;
    float a0 = 0.f, a1 = 0.f, a2 = 0.f, a3 = 0.f;
    for (int i = t; i < 512; i += 128) {
      float w = wrow[i];
      a0 = fmaf(w, x[i], a0);
      a1 = fmaf(w, x[512 + i], a1);
      a2 = fmaf(w, x[1024 + i], a2);
      a3 = fmaf(w, x[1536 + i], a3);
    }
#pragma unroll
    for (int o = 16; o; o >>= 1) {
      a0 += __shfl_xor_sync(~0u, a0, o);
      a1 += __shfl_xor_sync(~0u, a1, o);
      a2 += __shfl_xor_sync(~0u, a2, o);
      a3 += __shfl_xor_sync(~0u, a3, o);
    }
    __shared__ float sm[4][4];
    int wq = t >> 5, l = t & 31;
    if (l == 0) { sm[wq][0] = a0; sm[wq][1] = a1; sm[wq][2] = a2; sm[wq][3] = a3; }
    __syncthreads();
    if (t == 0) {
      float bb = cb[f];
#pragma unroll
      for (int b = 0; b < 4; b++)
        g_xt[b * 210 + f] = sm[0][b] + sm[1][b] + sm[2][b] + sm[3][b] + bb;
    }
  }
  __threadfence();
  __shared__ int slast;
  if (t == 0) slast = (atomicAdd(&g_ctr, 1) == 209);
  __syncthreads();
  if (!slast) return;
  __threadfence();
  if (t == 0) g_ctr = 0;  // reset for graph replay
  __shared__ float gated[4][105];
  for (int i = t; i < 420; i += 128) {
    int b = i / 105, k = i - 105 * b;
    float a1 = g_xt[b * 210 + k], a2 = g_xt[b * 210 + 105 + k];
    gated[b][k] = a1 * tanhf(a2);
  }
  __syncthreads();
  if (t < 64) {
    int b = t >> 4, r = (t >> 1) & 7, j = t & 1;
    int base = r * 12 + j * 2;
    float c0 = gated[b][base + 0] + 0.5f;
    float c1 = gated[b][base + 1];
    float bb0 = gated[b][base + 4];
    float bb1 = gated[b][base + 5];
    float s0 = gated[b][base + 8] + 1.0f;
    float s1 = gated[b][base + 9];
    float omc = 1.0f - c0;
    float p = s0 * omc + s1 * c1;
    float q = s0 * c1 - s1 * omc;
    float u = s0 * c0 - s1 * c1;
    float v = -(s0 * c1 + s1 * c0);
    float* dst = &g_acoef[((b * 8 + r) * 2 + j) * 6];
    dst[0] = bb0; dst[1] = bb1; dst[2] = p; dst[3] = q; dst[4] = u; dst[5] = v;
  }
  if (t < 4) {
    int b = t;
    float w[9];
#pragma unroll
    for (int i = 0; i < 9; i++) w[i] = gated[b][96 + i];
    w[8] += 0.35355339059327373f;  // 1/sqrt(8)
    float ss = 0.f;
#pragma unroll
    for (int i = 0; i < 9; i++) ss += w[i] * w[i];
    float inv = 1.0f / fmaxf(sqrtf(ss), 1e-12f);
    float mx = -3.4e38f;
#pragma unroll
    for (int i = 0; i < 9; i++) { w[i] *= inv; mx = fmaxf(mx, w[i]); }
    float sum = 0.f;
#pragma unroll
    for (int i = 0; i < 9; i++) { w[i] = expf(w[i] - mx); sum += w[i]; }
    float isum = 1.0f / sum;
#pragma unroll
    for (int i = 0; i < 8; i++) g_wr[b * 8 + i] = w[i] * isum;
  }
}

// w for one (b,r,pixel) given the 12 affine coefs and the 2 complex weights
__device__ __forceinline__ float wval(const float* c, float are, float aim,
                                      float bre, float bim,
                                      float a1re, float a1im, float b1re, float b1im) {
  float nr = c[0] + c[2] * are + c[3] * aim + c[4] * bre + c[5] * bim;
  float ni = c[1] - c[3] * are + c[2] * aim - c[5] * bre + c[4] * bim;
  float er = c[6] + c[8] * a1re + c[9] * a1im + c[10] * b1re + c[11] * b1im;
  float ei = c[7] - c[9] * a1re + c[8] * a1im - c[11] * b1re + c[10] * b1im;
  float d2 = er * er + ei * ei;
  float inv = rsqrtf(fmaxf(d2, 1e-12f));
  return (nr * er + ni * ei) * inv;
}

// triangular pair index: s <= t
#define TIDX(s, t) ((s) * 8 - (s) * ((s)-1) / 2 + ((t) - (s)))

// ---------------- K1: w-compute + Gram + dump, FRONT-BATCHED loads ----------
__global__ void __launch_bounds__(256, 2) k_gramB(const float* __restrict__ wt) {
  __shared__ float sw[32 * 256];   // 32 KB staging
  __shared__ float scf[384];
  __shared__ float red[8][44];
  int t = threadIdx.x;
  for (int i = t; i < 384; i += 256) scf[i] = g_acoef[i];
  __syncthreads();
  int n = blockIdx.x * 256 + t;             // pixel
  const float2* W2 = (const float2*)wt;
  // ---- phase 1a: batch ALL 32 weight loads (MLP=32 lines/warp) ----
  float2 L[32];
#pragma unroll
  for (int k = 0; k < 32; k++)
    L[k] = W2[(size_t)k * NPIX + n];
  // ---- phase 1b: compute w, stage to smem + dump to g_w ----
#pragma unroll
  for (int r = 0; r < 8; r++) {
    float2 A0 = L[4 * r + 0];
    float2 A1 = L[4 * r + 1];
    float2 B0 = L[4 * r + 2];
    float2 B1 = L[4 * r + 3];
#pragma unroll
    for (int b = 0; b < 4; b++) {
      const float* c = &scf[(b * 8 + r) * 12];
      float w = wval(c, A0.x, A0.y, B0.x, B0.y, A1.x, A1.y, B1.x, B1.y);
      sw[(b * 8 + r) * 256 + t] = w;
      g_w[(size_t)(b * 8 + r) * NPIX + n] = w;   // scratch for k_outD
    }
  }
  __syncthreads();
  // phase 2: warp (b, half) accumulates Gram + sums over 128 pixels
  int wq = t >> 5, lane = t & 31;
  int b = wq >> 1, half = wq & 1;
  float a[36], su[8];
#pragma unroll
  for (int k = 0; k < 36; k++) a[k] = 0.f;
#pragma unroll
  for (int k = 0; k < 8; k++) su[k] = 0.f;
#pragma unroll
  for (int k = 0; k < 4; k++) {
    int px = half * 128 + k * 32 + lane;
    float v[8];
#pragma unroll
    for (int s = 0; s < 8; s++) v[s] = sw[(b * 8 + s) * 256 + px];
#pragma unroll
    for (int s = 0; s < 8; s++) {
      su[s] += v[s];
#pragma unroll
      for (int u = s; u < 8; u++) a[TIDX(s, u)] = fmaf(v[s], v[u], a[TIDX(s, u)]);
    }
  }
#pragma unroll
  for (int k = 0; k < 36; k++)
#pragma unroll
    for (int o = 16; o; o >>= 1) a[k] += __shfl_xor_sync(~0u, a[k], o);
#pragma unroll
  for (int k = 0; k < 8; k++)
#pragma unroll
    for (int o = 16; o; o >>= 1) su[k] += __shfl_xor_sync(~0u, su[k], o);
  if (lane == 0) {
#pragma unroll
    for (int k = 0; k < 36; k++) red[wq][k] = a[k];
#pragma unroll
    for (int k = 0; k < 8; k++) red[wq][36 + k] = su[k];
  }
  __syncthreads();
  if (t < 176) {
    int bb = t / 44, j = t - 44 * bb;
    g_part[(size_t)(bb * 44 + j) * GBLK + blockIdx.x] =
        red[2 * bb][j] + red[2 * bb + 1][j];
  }
}

// ---------------- K2: reduce partials + finalize (4 blocks) ----------------
__global__ void __launch_bounds__(256) k_redfin() {
  int b = blockIdx.x;              // 0..3
  int t = threadIdx.x;             // 256 = 8 warps
  int wq = t >> 5, lane = t & 31;
  __shared__ float sG[44];
  for (int j = wq; j < 44; j += 8) {
    const float* p = &g_part[(size_t)(b * 44 + j) * GBLK];
    float acc = 0.f;
#pragma unroll
    for (int k = 0; k < GBLK / 32; k++) acc += p[k * 32 + lane];
#pragma unroll
    for (int o = 16; o; o >>= 1) acc += __shfl_xor_sync(~0u, acc, o);
    if (lane == 0) sG[j] = acc;
  }
  __syncthreads();
  if (t == 0) {
    float G[8][8], S[8];
#pragma unroll
    for (int s = 0; s < 8; s++)
#pragma unroll
      for (int u = s; u < 8; u++) { float g = sG[TIDX(s, u)]; G[s][u] = g; G[u][s] = g; }
#pragma unroll
    for (int s = 0; s < 8; s++) S[s] = sG[36 + s];
    float nc[8];
#pragma unroll
    for (int s = 0; s < 8; s++) nc[s] = fmaxf(sqrtf(G[s][s]), 1e-12f);
    float Gh[8][8];
#pragma unroll
    for (int s = 0; s < 8; s++)
#pragma unroll
      for (int u = 0; u < 8; u++) Gh[s][u] = G[s][u] / (nc[s] * nc[u]);
    const float alpha = 0.1f / (7.0f * 2.8284271247461903f);  // 0.1/(7*sqrt(8))
    float A[8][8];
#pragma unroll
    for (int s = 0; s < 8; s++)
#pragma unroll
      for (int u = 0; u < 8; u++) A[s][u] = (s == u) ? 1.0f : -alpha * Gh[s][u];
    float C[8], K = 0.f;
#pragma unroll
    for (int s = 0; s < 8; s++) C[s] = 0.f;
#pragma unroll
    for (int r = 0; r < 8; r++) {
      float q = 0.f;
#pragma unroll
      for (int u = 0; u < 8; u++) {
        float v = 0.f;
#pragma unroll
        for (int s = 0; s < 8; s++) v += A[r][s] * Gh[s][u];
        q += v * A[r][u];
      }
      float mc = fmaxf(sqrtf(fmaxf(q, 0.f)), 1e-12f);
      double meand = 0.0;
      float wr = g_wr[b * 8 + r];
#pragma unroll
      for (int s = 0; s < 8; s++) {
        float D = A[r][s] / (nc[s] * mc);
        C[s] += wr * D;
        meand += (double)D * (double)S[s];
      }
      meand /= (double)NPIX;
      double var = (1.0 - (double)NPIX * meand * meand) / (double)(NPIX - 1);
      if (var < 0.0) var = 0.0;
      double stdd = sqrt(var);
      if (stdd < 1e-12) stdd = 1e-12;
      g_Ff[b * 8 + r] = 0.01f * wr * (float)stdd;
      K += 0.01f * wr * (float)meand;
    }
#pragma unroll
    for (int s = 0; s < 8; s++) g_Cc[b * 8 + s] = C[s];
    g_Kk[b] = K;
  }
}

// ---------------- threefry2x32, round-adds on the FMA pipe (IMAD) ----------
__device__ __forceinline__ uint32_t addv(uint32_t a, uint32_t one, uint32_t b) {
  uint32_t d;
  asm("mad.lo.u32 %0, %1, %2, %3;" : "=r"(d) : "r"(a), "r"(one), "r"(b));
  return d;
}

__device__ __forceinline__ void threefry(uint32_t c0, uint32_t c1, uint32_t one,
                                         uint32_t& o0, uint32_t& o1) {
  const uint32_t K0 = 0u, K1 = 42u, K2 = 0x1BD11BDAu ^ 0u ^ 42u;
  uint32_t x0 = c0 + K0, x1 = c1 + K1;
#define TFR(rr) { x0 = addv(x0, one, x1); x1 = __funnelshift_l(x1, x1, rr); x1 ^= x0; }
  TFR(13) TFR(15) TFR(26) TFR(6)   x0 += K1; x1 += K2 + 1u;
  TFR(17) TFR(29) TFR(16) TFR(24)  x0 += K2; x1 += K0 + 2u;
  TFR(13) TFR(15) TFR(26) TFR(6)   x0 += K0; x1 += K1 + 3u;
  TFR(17) TFR(29) TFR(16) TFR(24)  x0 += K1; x1 += K2 + 4u;
  TFR(13) TFR(15) TFR(26) TFR(6)   x0 += K2; x1 += K0 + 5u;
#undef TFR
  o0 = x0; o1 = x1;
}

__device__ __forceinline__ float bits_to_normal(uint32_t bits) {
  float f = __uint_as_float((bits >> 9) | 0x3F800000u) - 1.0f;
  float x = fmaxf(-0.99999994f, fmaf(f, 2.0f, -0.99999994f));
  float w = -__logf(fmaf(x, -x, 1.0f));
  float p;
  if (w < 5.0f) {
    w -= 2.5f;
    p = 2.81022636e-08f;
    p = fmaf(p, w, 3.43273939e-07f);
    p = fmaf(p, w, -3.5233877e-06f);
    p = fmaf(p, w, -4.39150654e-06f);
    p = fmaf(p, w, 0.00021858087f);
    p = fmaf(p, w, -0.00125372503f);
    p = fmaf(p, w, -0.00417768164f);
    p = fmaf(p, w, 0.246640727f);
    p = fmaf(p, w, 1.50140941f);
  } else {
    w = sqrtf(w) - 3.0f;
    p = -0.000200214257f;
    p = fmaf(p, w, 0.000100950558f);
    p = fmaf(p, w, 0.00134934322f);
    p = fmaf(p, w, -0.00367342844f);
    p = fmaf(p, w, 0.00573950773f);
    p = fmaf(p, w, -0.0076224613f);
    p = fmaf(p, w, 0.00943887047f);
    p = fmaf(p, w, 1.00167406f);
    p = fmaf(p, w, 2.83297682f);
  }
  return 1.4142135623730951f * (p * x);
}

// ---------------- K3: (pixel, half) threads: scratch combine + inline noise -
__global__ void __launch_bounds__(256) k_outD(float* __restrict__ out) {
  __shared__ float sC[32], sF[32], sK[4];
  int t = threadIdx.x;
  if (t < 32) { sC[t] = g_Cc[t]; sF[t] = g_Ff[t]; }
  if (t < 4) sK[t] = g_Kk[t];
  __syncthreads();
  uint32_t one = blockDim.y;               // runtime 1 (opaque to ptxas)
  int h = t >> 7;                          // 0: batches {0,2}, 1: batches {1,3}
  int n = blockIdx.x * 128 + (t & 127);    // pixel
  float accA = sK[h], accB = sK[h + 2];
  float wA[8], wB[8];
#pragma unroll
  for (int r = 0; r < 8; r++) {
    wA[r] = g_w[(size_t)(h * 8 + r) * NPIX + n];
    wB[r] = g_w[(size_t)((h + 2) * 8 + r) * NPIX + n];
  }
#pragma unroll
  for (int r = 0; r < 8; r++) {
    accA = fmaf(sC[h * 8 + r], wA[r], accA);
    accB = fmaf(sC[(h + 2) * 8 + r], wB[r], accB);
  }
#pragma unroll
  for (int r = 0; r < 8; r++) {
    int j = h * 8 + r;                     // j>>3 == h
    uint32_t idx = ((uint32_t)j << 18) | (uint32_t)n;
    uint32_t o0, o1;
    threefry(idx, idx + HALFCNT, one, o0, o1);
    accA = fmaf(sF[j], bits_to_normal(o0), accA);        // batch h
    accB = fmaf(sF[j + 16], bits_to_normal(o1), accB);   // batch h+2
  }
  out[(size_t)h * NPIX + n] = accA;
  out[(size_t)(h + 2) * NPIX + n] = accB;
}

extern "C" void kernel_launch(void* const* d_in, const int* in_sizes, int n_in,
                              void* d_out, int out_size) {
  const float* x  = (const float*)d_in[0];
  const float* cw = (const float*)d_in[1];
  const float* cb = (const float*)d_in[2];
  const float* wt = (const float*)d_in[3];
  float* out = (float*)d_out;
  k_nop<<<1, 32>>>();                        // slot 1 (filler)
  k_nop<<<1, 32>>>();                        // slot 2 (filler)
  k_pre<<<210, 128>>>(x, cw, cb);            // slot 3
  k_gramB<<<GBLK, 256>>>(wt);                // slot 4  <-- profiled
  k_redfin<<<4, 256>>>();                    // slot 5
  k_outD<<<NPIX / 128, 256>>>(out);          // slot 6
}

// round 17
// speedup vs baseline: 1.1414x; 1.1414x over previous
#include <cuda_runtime.h>
#include <cuda_bf16.h>
#include <cstdint>

#define NPIX 262144               // 512*512 = 2^18
#define HALFCNT 4194304u          // 2^22 threefry counter half
#define GBLK 1024                 // k_gramB blocks (256 px each)

// ---------------- device scratch (allocation-free) ----------------
__device__ float g_xt[4 * 210];
__device__ float g_acoef[4 * 8 * 2 * 6];  // [b][r][j][bb0,bb1,p,q,u,v]
__device__ float g_wr[4 * 8];
__device__ float g_part[4 * 44 * GBLK];   // gram partials [b*44+j][blk]
__device__ float g_w[32 * NPIX];          // w[b*8+r][n] plane-major (32 MiB)
__device__ float g_Cc[4 * 8];
__device__ float g_Ff[4 * 8];
__device__ float g_Kk[4];
__device__ int   g_ctr;                   // last-block counter (reset each run)

// ---------------- K0: fused xt + mods (last block does mods) ----------------
__global__ void k_pre(const float* __restrict__ x, const float* __restrict__ cw,
                      const float* __restrict__ cb) {
  int f = blockIdx.x;          // 0..209
  int t = threadIdx.x;         // 128
  {
    const float* wrow = cw + f * 512;
    float a0 = 0.f, a1 = 0.f, a2 = 0.f, a3 = 0.f;
    for (int i = t; i < 512; i += 128) {
      float w = wrow[i];
      a0 = fmaf(w, x[i], a0);
      a1 = fmaf(w, x[512 + i], a1);
      a2 = fmaf(w, x[1024 + i], a2);
      a3 = fmaf(w, x[1536 + i], a3);
    }
#pragma unroll
    for (int o = 16; o; o >>= 1) {
      a0 += __shfl_xor_sync(~0u, a0, o);
      a1 += __shfl_xor_sync(~0u, a1, o);
      a2 += __shfl_xor_sync(~0u, a2, o);
      a3 += __shfl_xor_sync(~0u, a3, o);
    }
    __shared__ float sm[4][4];
    int wq = t >> 5, l = t & 31;
    if (l == 0) { sm[wq][0] = a0; sm[wq][1] = a1; sm[wq][2] = a2; sm[wq][3] = a3; }
    __syncthreads();
    if (t == 0) {
      float bb = cb[f];
#pragma unroll
      for (int b = 0; b < 4; b++)
        g_xt[b * 210 + f] = sm[0][b] + sm[1][b] + sm[2][b] + sm[3][b] + bb;
    }
  }
  __threadfence();
  __shared__ int slast;
  if (t == 0) slast = (atomicAdd(&g_ctr, 1) == 209);
  __syncthreads();
  if (!slast) return;
  __threadfence();
  if (t == 0) g_ctr = 0;  // reset for graph replay
  __shared__ float gated[4][105];
  for (int i = t; i < 420; i += 128) {
    int b = i / 105, k = i - 105 * b;
    float a1 = g_xt[b * 210 + k], a2 = g_xt[b * 210 + 105 + k];
    gated[b][k] = a1 * tanhf(a2);
  }
  __syncthreads();
  if (t < 64) {
    int b = t >> 4, r = (t >> 1) & 7, j = t & 1;
    int base = r * 12 + j * 2;
    float c0 = gated[b][base + 0] + 0.5f;
    float c1 = gated[b][base + 1];
    float bb0 = gated[b][base + 4];
    float bb1 = gated[b][base + 5];
    float s0 = gated[b][base + 8] + 1.0f;
    float s1 = gated[b][base + 9];
    float omc = 1.0f - c0;
    float p = s0 * omc + s1 * c1;
    float q = s0 * c1 - s1 * omc;
    float u = s0 * c0 - s1 * c1;
    float v = -(s0 * c1 + s1 * c0);
    float* dst = &g_acoef[((b * 8 + r) * 2 + j) * 6];
    dst[0] = bb0; dst[1] = bb1; dst[2] = p; dst[3] = q; dst[4] = u; dst[5] = v;
  }
  if (t < 4) {
    int b = t;
    float w[9];
#pragma unroll
    for (int i = 0; i < 9; i++) w[i] = gated[b][96 + i];
    w[8] += 0.35355339059327373f;  // 1/sqrt(8)
    float ss = 0.f;
#pragma unroll
    for (int i = 0; i < 9; i++) ss += w[i] * w[i];
    float inv = 1.0f / fmaxf(sqrtf(ss), 1e-12f);
    float mx = -3.4e38f;
#pragma unroll
    for (int i = 0; i < 9; i++) { w[i] *= inv; mx = fmaxf(mx, w[i]); }
    float sum = 0.f;
#pragma unroll
    for (int i = 0; i < 9; i++) { w[i] = expf(w[i] - mx); sum += w[i]; }
    float isum = 1.0f / sum;
#pragma unroll
    for (int i = 0; i < 8; i++) g_wr[b * 8 + i] = w[i] * isum;
  }
}

// w for one (b,r,pixel) given the 12 affine coefs and the 2 complex weights
__device__ __forceinline__ float wval(const float* c, float are, float aim,
                                      float bre, float bim,
                                      float a1re, float a1im, float b1re, float b1im) {
  float nr = c[0] + c[2] * are + c[3] * aim + c[4] * bre + c[5] * bim;
  float ni = c[1] - c[3] * are + c[2] * aim - c[5] * bre + c[4] * bim;
  float er = c[6] + c[8] * a1re + c[9] * a1im + c[10] * b1re + c[11] * b1im;
  float ei = c[7] - c[9] * a1re + c[8] * a1im - c[11] * b1re + c[10] * b1im;
  float d2 = er * er + ei * ei;
  float inv = rsqrtf(fmaxf(d2, 1e-12f));
  return (nr * er + ni * ei) * inv;
}

// triangular pair index: s <= t
#define TIDX(s, t) ((s) * 8 - (s) * ((s)-1) / 2 + ((t) - (s)))

// ---------------- K1: w-compute + Gram + dump, front-batched loads ----------
__global__ void __launch_bounds__(256) k_gramB(const float* __restrict__ wt) {
  __shared__ float sw[32 * 256];   // 32 KB staging
  __shared__ float scf[384];
  __shared__ float red[8][44];
  int t = threadIdx.x;
  for (int i = t; i < 384; i += 256) scf[i] = g_acoef[i];
  __syncthreads();
  int n = blockIdx.x * 256 + t;             // pixel
  const float2* W2 = (const float2*)wt;
  // ---- phase 1a: batch ALL 32 weight loads (MLP=32 lines/warp) ----
  float2 L[32];
#pragma unroll
  for (int k = 0; k < 32; k++)
    L[k] = W2[(size_t)k * NPIX + n];
  // ---- phase 1b: compute w, stage to smem + dump to g_w ----
#pragma unroll
  for (int r = 0; r < 8; r++) {
    float2 A0 = L[4 * r + 0];
    float2 A1 = L[4 * r + 1];
    float2 B0 = L[4 * r + 2];
    float2 B1 = L[4 * r + 3];
#pragma unroll
    for (int b = 0; b < 4; b++) {
      const float* c = &scf[(b * 8 + r) * 12];
      float w = wval(c, A0.x, A0.y, B0.x, B0.y, A1.x, A1.y, B1.x, B1.y);
      sw[(b * 8 + r) * 256 + t] = w;
      g_w[(size_t)(b * 8 + r) * NPIX + n] = w;   // scratch for k_outD
    }
  }
  __syncthreads();
  // phase 2: warp (b, half) accumulates Gram + sums over 128 pixels
  int wq = t >> 5, lane = t & 31;
  int b = wq >> 1, half = wq & 1;
  float a[36], su[8];
#pragma unroll
  for (int k = 0; k < 36; k++) a[k] = 0.f;
#pragma unroll
  for (int k = 0; k < 8; k++) su[k] = 0.f;
#pragma unroll
  for (int k = 0; k < 4; k++) {
    int px = half * 128 + k * 32 + lane;
    float v[8];
#pragma unroll
    for (int s = 0; s < 8; s++) v[s] = sw[(b * 8 + s) * 256 + px];
#pragma unroll
    for (int s = 0; s < 8; s++) {
      su[s] += v[s];
#pragma unroll
      for (int u = s; u < 8; u++) a[TIDX(s, u)] = fmaf(v[s], v[u], a[TIDX(s, u)]);
    }
  }
#pragma unroll
  for (int k = 0; k < 36; k++)
#pragma unroll
    for (int o = 16; o; o >>= 1) a[k] += __shfl_xor_sync(~0u, a[k], o);
#pragma unroll
  for (int k = 0; k < 8; k++)
#pragma unroll
    for (int o = 16; o; o >>= 1) su[k] += __shfl_xor_sync(~0u, su[k], o);
  if (lane == 0) {
#pragma unroll
    for (int k = 0; k < 36; k++) red[wq][k] = a[k];
#pragma unroll
    for (int k = 0; k < 8; k++) red[wq][36 + k] = su[k];
  }
  __syncthreads();
  if (t < 176) {
    int bb = t / 44, j = t - 44 * bb;
    g_part[(size_t)(bb * 44 + j) * GBLK + blockIdx.x] =
        red[2 * bb][j] + red[2 * bb + 1][j];
  }
}

// ---------------- K2: reduce partials + finalize (4 blocks) ----------------
__global__ void __launch_bounds__(256) k_redfin() {
  int b = blockIdx.x;              // 0..3
  int t = threadIdx.x;             // 256 = 8 warps
  int wq = t >> 5, lane = t & 31;
  __shared__ float sG[44];
  for (int j = wq; j < 44; j += 8) {
    const float* p = &g_part[(size_t)(b * 44 + j) * GBLK];
    float acc = 0.f;
#pragma unroll
    for (int k = 0; k < GBLK / 32; k++) acc += p[k * 32 + lane];
#pragma unroll
    for (int o = 16; o; o >>= 1) acc += __shfl_xor_sync(~0u, acc, o);
    if (lane == 0) sG[j] = acc;
  }
  __syncthreads();
  if (t == 0) {
    float G[8][8], S[8];
#pragma unroll
    for (int s = 0; s < 8; s++)
#pragma unroll
      for (int u = s; u < 8; u++) { float g = sG[TIDX(s, u)]; G[s][u] = g; G[u][s] = g; }
#pragma unroll
    for (int s = 0; s < 8; s++) S[s] = sG[36 + s];
    float nc[8];
#pragma unroll
    for (int s = 0; s < 8; s++) nc[s] = fmaxf(sqrtf(G[s][s]), 1e-12f);
    float Gh[8][8];
#pragma unroll
    for (int s = 0; s < 8; s++)
#pragma unroll
      for (int u = 0; u < 8; u++) Gh[s][u] = G[s][u] / (nc[s] * nc[u]);
    const float alpha = 0.1f / (7.0f * 2.8284271247461903f);  // 0.1/(7*sqrt(8))
    float A[8][8];
#pragma unroll
    for (int s = 0; s < 8; s++)
#pragma unroll
      for (int u = 0; u < 8; u++) A[s][u] = (s == u) ? 1.0f : -alpha * Gh[s][u];
    float C[8], K = 0.f;
#pragma unroll
    for (int s = 0; s < 8; s++) C[s] = 0.f;
#pragma unroll
    for (int r = 0; r < 8; r++) {
      float q = 0.f;
#pragma unroll
      for (int u = 0; u < 8; u++) {
        float v = 0.f;
#pragma unroll
        for (int s = 0; s < 8; s++) v += A[r][s] * Gh[s][u];
        q += v * A[r][u];
      }
      float mc = fmaxf(sqrtf(fmaxf(q, 0.f)), 1e-12f);
      double meand = 0.0;
      float wr = g_wr[b * 8 + r];
#pragma unroll
      for (int s = 0; s < 8; s++) {
        float D = A[r][s] / (nc[s] * mc);
        C[s] += wr * D;
        meand += (double)D * (double)S[s];
      }
      meand /= (double)NPIX;
      double var = (1.0 - (double)NPIX * meand * meand) / (double)(NPIX - 1);
      if (var < 0.0) var = 0.0;
      double stdd = sqrt(var);
      if (stdd < 1e-12) stdd = 1e-12;
      g_Ff[b * 8 + r] = 0.01f * wr * (float)stdd;
      K += 0.01f * wr * (float)meand;
    }
#pragma unroll
    for (int s = 0; s < 8; s++) g_Cc[b * 8 + s] = C[s];
    g_Kk[b] = K;
  }
}

// ---------------- threefry2x32, round-adds on the FMA pipe (IMAD) ----------
__device__ __forceinline__ uint32_t addv(uint32_t a, uint32_t one, uint32_t b) {
  uint32_t d;
  asm("mad.lo.u32 %0, %1, %2, %3;" : "=r"(d) : "r"(a), "r"(one), "r"(b));
  return d;
}

__device__ __forceinline__ void threefry(uint32_t c0, uint32_t c1, uint32_t one,
                                         uint32_t& o0, uint32_t& o1) {
  const uint32_t K0 = 0u, K1 = 42u, K2 = 0x1BD11BDAu ^ 0u ^ 42u;
  uint32_t x0 = c0 + K0, x1 = c1 + K1;
#define TFR(rr) { x0 = addv(x0, one, x1); x1 = __funnelshift_l(x1, x1, rr); x1 ^= x0; }
  TFR(13) TFR(15) TFR(26) TFR(6)   x0 += K1; x1 += K2 + 1u;
  TFR(17) TFR(29) TFR(16) TFR(24)  x0 += K2; x1 += K0 + 2u;
  TFR(13) TFR(15) TFR(26) TFR(6)   x0 += K0; x1 += K1 + 3u;
  TFR(17) TFR(29) TFR(16) TFR(24)  x0 += K1; x1 += K2 + 4u;
  TFR(13) TFR(15) TFR(26) TFR(6)   x0 += K2; x1 += K0 + 5u;
#undef TFR
  o0 = x0; o1 = x1;
}

__device__ __forceinline__ float bits_to_normal(uint32_t bits) {
  float f = __uint_as_float((bits >> 9) | 0x3F800000u) - 1.0f;
  float x = fmaxf(-0.99999994f, fmaf(f, 2.0f, -0.99999994f));
  float w = -__logf(fmaf(x, -x, 1.0f));
  float p;
  if (w < 5.0f) {
    w -= 2.5f;
    p = 2.81022636e-08f;
    p = fmaf(p, w, 3.43273939e-07f);
    p = fmaf(p, w, -3.5233877e-06f);
    p = fmaf(p, w, -4.39150654e-06f);
    p = fmaf(p, w, 0.00021858087f);
    p = fmaf(p, w, -0.00125372503f);
    p = fmaf(p, w, -0.00417768164f);
    p = fmaf(p, w, 0.246640727f);
    p = fmaf(p, w, 1.50140941f);
  } else {
    w = sqrtf(w) - 3.0f;
    p = -0.000200214257f;
    p = fmaf(p, w, 0.000100950558f);
    p = fmaf(p, w, 0.00134934322f);
    p = fmaf(p, w, -0.00367342844f);
    p = fmaf(p, w, 0.00573950773f);
    p = fmaf(p, w, -0.0076224613f);
    p = fmaf(p, w, 0.00943887047f);
    p = fmaf(p, w, 1.00167406f);
    p = fmaf(p, w, 2.83297682f);
  }
  return 1.4142135623730951f * (p * x);
}

// ---------------- K3: (pixel, half) threads: scratch combine + inline noise -
__global__ void __launch_bounds__(256) k_outD(float* __restrict__ out) {
  __shared__ float sC[32], sF[32], sK[4];
  int t = threadIdx.x;
  if (t < 32) { sC[t] = g_Cc[t]; sF[t] = g_Ff[t]; }
  if (t < 4) sK[t] = g_Kk[t];
  __syncthreads();
  uint32_t one = blockDim.y;               // runtime 1 (opaque to ptxas)
  int h = t >> 7;                          // 0: batches {0,2}, 1: batches {1,3}
  int n = blockIdx.x * 128 + (t & 127);    // pixel
  float accA = sK[h], accB = sK[h + 2];
  float wA[8], wB[8];
#pragma unroll
  for (int r = 0; r < 8; r++) {
    wA[r] = g_w[(size_t)(h * 8 + r) * NPIX + n];
    wB[r] = g_w[(size_t)((h + 2) * 8 + r) * NPIX + n];
  }
#pragma unroll
  for (int r = 0; r < 8; r++) {
    accA = fmaf(sC[h * 8 + r], wA[r], accA);
    accB = fmaf(sC[(h + 2) * 8 + r], wB[r], accB);
  }
#pragma unroll
  for (int r = 0; r < 8; r++) {
    int j = h * 8 + r;                     // j>>3 == h
    uint32_t idx = ((uint32_t)j << 18) | (uint32_t)n;
    uint32_t o0, o1;
    threefry(idx, idx + HALFCNT, one, o0, o1);
    accA = fmaf(sF[j], bits_to_normal(o0), accA);        // batch h
    accB = fmaf(sF[j + 16], bits_to_normal(o1), accB);   // batch h+2
  }
  out[(size_t)h * NPIX + n] = accA;
  out[(size_t)(h + 2) * NPIX + n] = accB;
}

extern "C" void kernel_launch(void* const* d_in, const int* in_sizes, int n_in,
                              void* d_out, int out_size) {
  const float* x  = (const float*)d_in[0];
  const float* cw = (const float*)d_in[1];
  const float* cb = (const float*)d_in[2];
  const float* wt = (const float*)d_in[3];
  float* out = (float*)d_out;
  k_pre<<<210, 128>>>(x, cw, cb);            // launch 1
  k_gramB<<<GBLK, 256>>>(wt);                // launch 2
  k_redfin<<<4, 256>>>();                    // launch 3
  k_outD<<<NPIX / 128, 256>>>(out);          // launch 4
}